// round 1
// baseline (speedup 1.0000x reference)
#include <cuda_runtime.h>
#include <math_constants.h>

// Problem shape (fixed for this problem id)
#define Bdim 2048
#define Ddim 25088
#define Cdim 100

#define SPLITS 16
#define BM 64
#define BN 128
#define BK 16
#define KCHUNK (Ddim / SPLITS)   // 1568
#define KTILES (KCHUNK / BK)     // 98

// -------- scratch (static __device__, no allocations) --------
__device__ float g_part[(size_t)SPLITS * Bdim * BN];   // 16 MB partial dots
__device__ float g_nfsq[SPLITS * 4 * Bdim];            // feature norm^2 partials
__device__ float g_wn[BN];                             // weight row norms
__device__ float g_nll[Bdim];
__device__ float g_corr[Bdim];
__device__ float g_vld[Bdim];
__device__ int   g_is64;

// -------- packed fp32x2 helpers (Blackwell FFMA2 only via PTX) --------
__device__ __forceinline__ unsigned long long pk2(float lo, float hi) {
    unsigned long long r;
    asm("mov.b64 %0, {%1, %2};" : "=l"(r) : "f"(lo), "f"(hi));
    return r;
}
__device__ __forceinline__ void ffma2(unsigned long long& d,
                                      unsigned long long a,
                                      unsigned long long b) {
    asm("fma.rn.f32x2 %0, %1, %2, %0;" : "+l"(d) : "l"(a), "l"(b));
}

// ======================= label dtype sniffing =======================
// jax randint(dtype=int64) silently becomes int32 without x64 — detect which
// layout the buffer actually has. Values are in [0,100) (or -1), so for int64
// the high 32-bit words are 0 or -1; for int32 the odd words are labels
// (P(all 64 sampled odd words in {0,-1}) ~ 1e-128).
__global__ void detect_label_kernel(const int* __restrict__ l32, int nlab) {
    if (threadIdx.x == 0 && blockIdx.x == 0) {
        int n = nlab < 64 ? nlab : 64;
        int is64 = 1;
        for (int j = 0; j < n; j++) {
            int hi = l32[2 * j + 1];
            if (hi != 0 && hi != -1) { is64 = 0; break; }
        }
        g_is64 = is64;
    }
}

// ======================= weight row norms =======================
__global__ __launch_bounds__(256) void wnorm_kernel(const float* __restrict__ W) {
    const int c = blockIdx.x;            // 0..BN-1 (c >= Cdim -> eps)
    __shared__ float red[256];
    float s = 0.f;
    if (c < Cdim) {
        const float4* row = (const float4*)(W + (size_t)c * Ddim);
        for (int i = threadIdx.x; i < Ddim / 4; i += 256) {
            float4 v = row[i];
            s += v.x * v.x + v.y * v.y + v.z * v.z + v.w * v.w;
        }
    }
    red[threadIdx.x] = s;
    __syncthreads();
    for (int off = 128; off > 0; off >>= 1) {
        if (threadIdx.x < off) red[threadIdx.x] += red[threadIdx.x + off];
        __syncthreads();
    }
    if (threadIdx.x == 0) g_wn[c] = fmaxf(sqrtf(red[0]), 1e-8f);
}

// ======================= split-K fp32 GEMM (FFMA2) =======================
// grid: (Bdim/BM, SPLITS), 256 threads.
// Each block: BM x BN output tile over one K chunk, register tile 4(m) x 8(n)
// as 4x4 packed-f32x2 accumulators. Feature norm^2 fused into the A loader.
__global__ __launch_bounds__(256) void gemm_kernel(const float* __restrict__ F,
                                                   const float* __restrict__ W) {
    __shared__ float as[BK][BM + 4];
    __shared__ float bs[BK][BN + 4];

    const int t     = threadIdx.x;
    const int m0    = blockIdx.x * BM;
    const int split = blockIdx.y;
    const int k0    = split * KCHUNK;

    // loader mapping
    const int a_row = t >> 2;        // 0..63 (fixed row per thread!)
    const int a_seg = t & 3;         // 0..3  (16B segment within BK)
    const int b_c0  = t >> 2;        // weight rows 0..63
    const int b_c1  = (t + 256) >> 2;// weight rows 64..127
    const int b_seg = t & 3;

    // compute mapping: 16 x 16 thread grid, frag 4(m) x 8(n)
    const int tm = t >> 4;
    const int tn = t & 15;

    unsigned long long acc[4][4];
#pragma unroll
    for (int i = 0; i < 4; i++)
#pragma unroll
        for (int p = 0; p < 4; p++) acc[i][p] = 0ULL;

    float nfacc = 0.f;

    const float* fptr  = F + (size_t)(m0 + a_row) * Ddim + k0 + a_seg * 4;
    const float* wptr0 = (b_c0 < Cdim) ? (W + (size_t)b_c0 * Ddim + k0 + b_seg * 4) : 0;
    const float* wptr1 = (b_c1 < Cdim) ? (W + (size_t)b_c1 * Ddim + k0 + b_seg * 4) : 0;

    for (int kt = 0; kt < KTILES; kt++) {
        // prefetch globals before the barrier
        float4 av  = *(const float4*)(fptr + kt * BK);
        float4 bv0 = wptr0 ? *(const float4*)(wptr0 + kt * BK) : make_float4(0.f, 0.f, 0.f, 0.f);
        float4 bv1 = wptr1 ? *(const float4*)(wptr1 + kt * BK) : make_float4(0.f, 0.f, 0.f, 0.f);
        nfacc += av.x * av.x + av.y * av.y + av.z * av.z + av.w * av.w;

        __syncthreads();   // previous tile's compute done
        as[a_seg * 4 + 0][a_row] = av.x;
        as[a_seg * 4 + 1][a_row] = av.y;
        as[a_seg * 4 + 2][a_row] = av.z;
        as[a_seg * 4 + 3][a_row] = av.w;
        bs[b_seg * 4 + 0][b_c0] = bv0.x;
        bs[b_seg * 4 + 1][b_c0] = bv0.y;
        bs[b_seg * 4 + 2][b_c0] = bv0.z;
        bs[b_seg * 4 + 3][b_c0] = bv0.w;
        bs[b_seg * 4 + 0][b_c1] = bv1.x;
        bs[b_seg * 4 + 1][b_c1] = bv1.y;
        bs[b_seg * 4 + 2][b_c1] = bv1.z;
        bs[b_seg * 4 + 3][b_c1] = bv1.w;
        __syncthreads();

#pragma unroll
        for (int k = 0; k < BK; k++) {
            float4 a4 = *(const float4*)&as[k][tm * 4];
            unsigned long long ap0 = pk2(a4.x, a4.x);
            unsigned long long ap1 = pk2(a4.y, a4.y);
            unsigned long long ap2 = pk2(a4.z, a4.z);
            unsigned long long ap3 = pk2(a4.w, a4.w);
            const unsigned long long* bp =
                (const unsigned long long*)&bs[k][tn * 8];
            unsigned long long b0 = bp[0], b1 = bp[1], b2 = bp[2], b3 = bp[3];
            ffma2(acc[0][0], ap0, b0); ffma2(acc[0][1], ap0, b1);
            ffma2(acc[0][2], ap0, b2); ffma2(acc[0][3], ap0, b3);
            ffma2(acc[1][0], ap1, b0); ffma2(acc[1][1], ap1, b1);
            ffma2(acc[1][2], ap1, b2); ffma2(acc[1][3], ap1, b3);
            ffma2(acc[2][0], ap2, b0); ffma2(acc[2][1], ap2, b1);
            ffma2(acc[2][2], ap2, b2); ffma2(acc[2][3], ap2, b3);
            ffma2(acc[3][0], ap3, b0); ffma2(acc[3][1], ap3, b1);
            ffma2(acc[3][2], ap3, b2); ffma2(acc[3][3], ap3, b3);
        }
    }

    // write partial dots (deterministic, per-slot)
#pragma unroll
    for (int i = 0; i < 4; i++) {
        const int row = m0 + tm * 4 + i;
        unsigned long long* dst = (unsigned long long*)
            &g_part[((size_t)split * Bdim + row) * BN + tn * 8];
#pragma unroll
        for (int p = 0; p < 4; p++) dst[p] = acc[i][p];
    }
    // fused feature norm^2 partial (one writer per (split, seg, row))
    g_nfsq[(split * 4 + a_seg) * Bdim + (m0 + a_row)] = nfacc;
}

// ======================= per-row epilogue =======================
// grid: Bdim blocks, 128 threads. cos logits, argmax (first-index tie like
// jnp.argmax), log-sum-exp, per-row NLL/correct/valid.
__global__ __launch_bounds__(128) void epilogue_kernel(const void* __restrict__ labels) {
    const int row = blockIdx.x;
    const int t   = threadIdx.x;

    __shared__ float sv[128];
    __shared__ int   si[128];
    __shared__ float slog[128];
    __shared__ float s_nf;

    if (t == 0) {
        float s = 0.f;
        for (int i = 0; i < SPLITS * 4; i++) s += g_nfsq[i * Bdim + row];
        s_nf = fmaxf(sqrtf(s), 1e-8f);
    }
    __syncthreads();

    float logit = -CUDART_INF_F;
    if (t < Cdim) {
        float g = 0.f;
        for (int s = 0; s < SPLITS; s++)
            g += g_part[((size_t)s * Bdim + row) * BN + t];
        logit = 10.0f * g / (s_nf * g_wn[t]);
    }
    slog[t] = logit;
    sv[t]   = logit;
    si[t]   = t;
    __syncthreads();

    // max + first-index argmax
    for (int off = 64; off > 0; off >>= 1) {
        if (t < off) {
            float v2 = sv[t + off]; int i2 = si[t + off];
            if (v2 > sv[t] || (v2 == sv[t] && i2 < si[t])) { sv[t] = v2; si[t] = i2; }
        }
        __syncthreads();
    }
    const float mx   = sv[0];
    const int   amax = si[0];
    __syncthreads();

    sv[t] = (t < Cdim) ? expf(logit - mx) : 0.f;
    __syncthreads();
    for (int off = 64; off > 0; off >>= 1) {
        if (t < off) sv[t] += sv[t + off];
        __syncthreads();
    }

    if (t == 0) {
        const float lse = logf(sv[0]) + mx;
        long long lab;
        if (g_is64) lab = ((const long long*)labels)[row];
        else        lab = (long long)((const int*)labels)[row];
        const bool valid = (lab >= 0);
        float nll = 0.f, corr = 0.f;
        if (valid) {
            nll  = lse - slog[(int)lab];
            corr = (amax == (int)lab) ? 1.f : 0.f;
        }
        g_nll[row]  = nll;
        g_corr[row] = corr;
        g_vld[row]  = valid ? 1.f : 0.f;
    }
}

// ======================= finalize =======================
__global__ __launch_bounds__(256) void finalize_kernel(float* __restrict__ out,
                                                       int out_size) {
    __shared__ float sn[256], sc[256], sd[256];
    const int t = threadIdx.x;
    float a = 0.f, b = 0.f, c = 0.f;
    for (int i = t; i < Bdim; i += 256) {
        a += g_nll[i]; b += g_corr[i]; c += g_vld[i];
    }
    sn[t] = a; sc[t] = b; sd[t] = c;
    __syncthreads();
    for (int off = 128; off > 0; off >>= 1) {
        if (t < off) { sn[t] += sn[t + off]; sc[t] += sc[t + off]; sd[t] += sd[t + off]; }
        __syncthreads();
    }
    if (t == 0) {
        const float nv   = sd[0];
        const float loss = sn[0] / fmaxf(nv, 1.0f);
        const float acc  = sc[0] / (nv + 1e-10f);
        out[0] = loss;
        if (out_size > 1) out[1] = acc;
    }
}

// ======================= launch =======================
extern "C" void kernel_launch(void* const* d_in, const int* in_sizes, int n_in,
                              void* d_out, int out_size) {
    // identify inputs by element count (robust to metadata order):
    // feature = largest, label = smallest, weight = the remaining one.
    int fi = 0, li = 0;
    for (int i = 1; i < n_in; i++) {
        if (in_sizes[i] > in_sizes[fi]) fi = i;
        if (in_sizes[i] < in_sizes[li]) li = i;
    }
    int wi = 0;
    for (int i = 0; i < n_in; i++) if (i != fi && i != li) wi = i;

    const float* F = (const float*)d_in[fi];
    const float* W = (const float*)d_in[wi];
    const void*  L = d_in[li];
    const int nlab = in_sizes[li];

    detect_label_kernel<<<1, 32>>>((const int*)L, nlab);
    wnorm_kernel<<<BN, 256>>>(W);
    gemm_kernel<<<dim3(Bdim / BM, SPLITS), 256>>>(F, W);
    epilogue_kernel<<<Bdim, 128>>>(L);
    finalize_kernel<<<1, 256>>>((float*)d_out, out_size);
}

// round 3
// speedup vs baseline: 7.3479x; 7.3479x over previous
#include <cuda_runtime.h>
#include <math_constants.h>
#include <cstdint>

// Problem shape (fixed)
#define Bdim 2048
#define Ddim 25088
#define Cdim 100
#define CPAD 128

#define SPLITS 8
#define KC (Ddim / SPLITS)      // 3136
#define KT 32                   // bf16 K per iteration
#define ITERS (KC / KT)         // 98
#define BM 128

// smem tile geometry: 128 rows x 32 bf16, row stride padded to 80 B
#define STR 80
#define TILE_SZ (128 * STR)              // 10240 B
#define BUF_SZ (4 * TILE_SZ)             // Ahi, Alo, Bhi, Blo = 40960 B
#define SMEM_TOTAL (2 * BUF_SZ)          // 81920 B

// ---------------- scratch ----------------
__device__ float g_part[(size_t)SPLITS * Bdim * CPAD];  // 8 MB split partials
__device__ float g_nfsq[SPLITS * 4 * Bdim];             // feature norm^2 partials
__device__ float g_wn[CPAD];
__device__ float g_nll[Bdim];
__device__ float g_corr[Bdim];
__device__ float g_vld[Bdim];
__device__ int   g_is64;

// ---------------- helpers ----------------
__device__ __forceinline__ uint32_t smem_u32(const void* p) {
    uint32_t a;
    asm("{ .reg .u64 t; cvta.to.shared.u64 t, %1; cvt.u32.u64 %0, t; }" : "=r"(a) : "l"(p));
    return a;
}
__device__ __forceinline__ void ldsm4(uint32_t addr, uint32_t& r0, uint32_t& r1,
                                      uint32_t& r2, uint32_t& r3) {
    asm volatile("ldmatrix.sync.aligned.m8n8.x4.shared.b16 {%0,%1,%2,%3}, [%4];"
                 : "=r"(r0), "=r"(r1), "=r"(r2), "=r"(r3) : "r"(addr));
}
__device__ __forceinline__ void mma_bf16(float& d0, float& d1, float& d2, float& d3,
                                         uint32_t a0, uint32_t a1, uint32_t a2, uint32_t a3,
                                         uint32_t b0, uint32_t b1) {
    asm volatile("mma.sync.aligned.m16n8k16.row.col.f32.bf16.bf16.f32 "
                 "{%0,%1,%2,%3}, {%4,%5,%6,%7}, {%8,%9}, {%0,%1,%2,%3};"
                 : "+f"(d0), "+f"(d1), "+f"(d2), "+f"(d3)
                 : "r"(a0), "r"(a1), "r"(a2), "r"(a3), "r"(b0), "r"(b1));
}
// pack 2 floats -> bf16x2 hi, residuals -> bf16x2 lo
__device__ __forceinline__ void cvt2(float x, float y, uint32_t& hi, uint32_t& lo) {
    asm("cvt.rn.bf16x2.f32 %0, %1, %2;" : "=r"(hi) : "f"(y), "f"(x));
    float fx = __uint_as_float(hi << 16);
    float fy = __uint_as_float(hi & 0xFFFF0000u);
    asm("cvt.rn.bf16x2.f32 %0, %1, %2;" : "=r"(lo) : "f"(y - fy), "f"(x - fx));
}

// ======================= HMMA split-bf16 GEMM =======================
// grid (Bdim/BM, SPLITS), 512 threads. Warp grid 4(M) x 4(N), warp tile 32x32.
__global__ void __launch_bounds__(512, 1)
gemm_mma_kernel(const float* __restrict__ F, const float* __restrict__ W) {
    extern __shared__ char smem[];
    const uint32_t sbase = smem_u32(smem);

    const int t     = threadIdx.x;
    const int lane  = t & 31;
    const int w     = t >> 5;
    const int m0    = blockIdx.x * BM;
    const int split = blockIdx.y;
    const int k0    = split * KC;

    // ---- loader mapping: row = t/4 (0..127), quarter q = t%3.. t&3 (8 floats) ----
    const int row = t >> 2;
    const int q   = t & 3;
    const bool liveB = (row < Cdim);

    const float4* gA = (const float4*)(F + (size_t)(m0 + row) * Ddim + k0) + 2 * q;
    const float4* gB = liveB ? (const float4*)(W + (size_t)row * Ddim + k0) + 2 * q : nullptr;
    const uint32_t stsA = sbase + row * STR + q * 16;              // within Ahi tile
    const uint32_t stsB = sbase + 2 * TILE_SZ + row * STR + q * 16;

    // ---- MMA mapping ----
    const int wm = w >> 2;   // 0..3 -> rows wm*32
    const int wn = w & 3;    // 0..3 -> cols wn*32
    // A ldmatrix lane address (within Ahi tile), for (mi, ks):
    //   (wm*32 + mi*16 + (lane&15))*STR + ks*32 + (lane>>4)*16
    const uint32_t aAddr0 = sbase + (wm * 32 + (lane & 15)) * STR + (lane >> 4) * 16;
    // B ldmatrix lane address (within Bhi tile), for (ni2, ks):
    //   (wn*32 + ni2*16 + (lane&7) + (lane>>4)*8)*STR + ks*32 + ((lane>>3)&1)*16
    const uint32_t bAddr0 = sbase + 2 * TILE_SZ +
        (wn * 32 + (lane & 7) + (lane >> 4) * 8) * STR + ((lane >> 3) & 1) * 16;

    float acc[2][4][4];
#pragma unroll
    for (int i = 0; i < 2; i++)
#pragma unroll
        for (int j = 0; j < 4; j++)
#pragma unroll
            for (int e = 0; e < 4; e++) acc[i][j][e] = 0.f;

    float nf = 0.f;
    float4 ra0, ra1, rb0, rb1;

    // prologue load tile 0
    ra0 = gA[0]; ra1 = gA[1];
    if (liveB) { rb0 = gB[0]; rb1 = gB[1]; }
    else       { rb0 = rb1 = make_float4(0.f, 0.f, 0.f, 0.f); }

    for (int it = 0; it < ITERS; it++) {
        const uint32_t bufo = (it & 1) ? BUF_SZ : 0;

        __syncthreads();   // prior reads of this buffer complete

        // convert + store current tile
        nf += ra0.x * ra0.x + ra0.y * ra0.y + ra0.z * ra0.z + ra0.w * ra0.w
            + ra1.x * ra1.x + ra1.y * ra1.y + ra1.z * ra1.z + ra1.w * ra1.w;
        {
            uint32_t h0, h1, h2, h3, l0, l1, l2, l3;
            cvt2(ra0.x, ra0.y, h0, l0); cvt2(ra0.z, ra0.w, h1, l1);
            cvt2(ra1.x, ra1.y, h2, l2); cvt2(ra1.z, ra1.w, h3, l3);
            *(uint4*)(smem + (stsA - sbase) + bufo) = make_uint4(h0, h1, h2, h3);
            *(uint4*)(smem + (stsA - sbase) + bufo + TILE_SZ) = make_uint4(l0, l1, l2, l3);
            cvt2(rb0.x, rb0.y, h0, l0); cvt2(rb0.z, rb0.w, h1, l1);
            cvt2(rb1.x, rb1.y, h2, l2); cvt2(rb1.z, rb1.w, h3, l3);
            *(uint4*)(smem + (stsB - sbase) + bufo) = make_uint4(h0, h1, h2, h3);
            *(uint4*)(smem + (stsB - sbase) + bufo + TILE_SZ) = make_uint4(l0, l1, l2, l3);
        }
        __syncthreads();   // tile visible

        // prefetch next tile into regs (hidden under MMA work)
        if (it + 1 < ITERS) {
            ra0 = gA[(it + 1) * 8];     ra1 = gA[(it + 1) * 8 + 1];
            if (liveB) { rb0 = gB[(it + 1) * 8]; rb1 = gB[(it + 1) * 8 + 1]; }
        }

        // MMA over this buffer: 2 k16 steps x (2 m-frags x 2 n16-groups) x 3 terms
#pragma unroll
        for (int ks = 0; ks < 2; ks++) {
            uint32_t ah[2][4], al[2][4], bh[2][4], bl[2][4];
#pragma unroll
            for (int mi = 0; mi < 2; mi++) {
                const uint32_t a = aAddr0 + bufo + mi * 16 * STR + ks * 32;
                ldsm4(a,            ah[mi][0], ah[mi][1], ah[mi][2], ah[mi][3]);
                ldsm4(a + TILE_SZ,  al[mi][0], al[mi][1], al[mi][2], al[mi][3]);
            }
#pragma unroll
            for (int ni = 0; ni < 2; ni++) {
                const uint32_t b = bAddr0 + bufo + ni * 16 * STR + ks * 32;
                ldsm4(b,            bh[ni][0], bh[ni][1], bh[ni][2], bh[ni][3]);
                ldsm4(b + TILE_SZ,  bl[ni][0], bl[ni][1], bl[ni][2], bl[ni][3]);
            }
#pragma unroll
            for (int mi = 0; mi < 2; mi++)
#pragma unroll
                for (int ni = 0; ni < 2; ni++)
#pragma unroll
                    for (int h = 0; h < 2; h++) {  // n8 half within n16 group
                        float* d = acc[mi][ni * 2 + h];
                        const uint32_t b0 = bh[ni][2 * h], b1 = bh[ni][2 * h + 1];
                        const uint32_t c0 = bl[ni][2 * h], c1 = bl[ni][2 * h + 1];
                        mma_bf16(d[0], d[1], d[2], d[3],
                                 ah[mi][0], ah[mi][1], ah[mi][2], ah[mi][3], b0, b1);
                        mma_bf16(d[0], d[1], d[2], d[3],
                                 ah[mi][0], ah[mi][1], ah[mi][2], ah[mi][3], c0, c1);
                        mma_bf16(d[0], d[1], d[2], d[3],
                                 al[mi][0], al[mi][1], al[mi][2], al[mi][3], b0, b1);
                    }
        }
    }

    // feature norm^2 partial
    g_nfsq[(split * 4 + q) * Bdim + (m0 + row)] = nf;

    // write partials: thread holds acc[mi][nj][e]
    // row = m0 + wm*32 + mi*16 + (lane>>2) + (e>>1)*8 ; col = wn*32 + nj*8 + (lane&3)*2 + (e&1)
#pragma unroll
    for (int mi = 0; mi < 2; mi++)
#pragma unroll
        for (int nj = 0; nj < 4; nj++)
#pragma unroll
            for (int e = 0; e < 4; e++) {
                const int r = m0 + wm * 32 + mi * 16 + (lane >> 2) + (e >> 1) * 8;
                const int c = wn * 32 + nj * 8 + (lane & 3) * 2 + (e & 1);
                g_part[((size_t)split * Bdim + r) * CPAD + c] = acc[mi][nj][e];
            }
}

// ======================= label dtype sniffing =======================
__global__ void detect_label_kernel(const int* __restrict__ l32, int nlab) {
    if (threadIdx.x == 0 && blockIdx.x == 0) {
        int n = nlab < 64 ? nlab : 64;
        int is64 = 1;
        for (int j = 0; j < n; j++) {
            int hi = l32[2 * j + 1];
            if (hi != 0 && hi != -1) { is64 = 0; break; }
        }
        g_is64 = is64;
    }
}

// ======================= weight row norms =======================
__global__ __launch_bounds__(256) void wnorm_kernel(const float* __restrict__ W) {
    const int c = blockIdx.x;
    __shared__ float red[256];
    float s = 0.f;
    if (c < Cdim) {
        const float4* row = (const float4*)(W + (size_t)c * Ddim);
        for (int i = threadIdx.x; i < Ddim / 4; i += 256) {
            float4 v = row[i];
            s += v.x * v.x + v.y * v.y + v.z * v.z + v.w * v.w;
        }
    }
    red[threadIdx.x] = s;
    __syncthreads();
    for (int off = 128; off > 0; off >>= 1) {
        if (threadIdx.x < off) red[threadIdx.x] += red[threadIdx.x + off];
        __syncthreads();
    }
    if (threadIdx.x == 0) g_wn[c] = fmaxf(sqrtf(red[0]), 1e-8f);
}

// ======================= per-row epilogue =======================
__global__ __launch_bounds__(128) void epilogue_kernel(const void* __restrict__ labels) {
    const int row = blockIdx.x;
    const int t   = threadIdx.x;

    __shared__ float sv[128];
    __shared__ int   si[128];
    __shared__ float slog[128];
    __shared__ float s_nf;

    if (t == 0) {
        float s = 0.f;
        for (int i = 0; i < SPLITS * 4; i++) s += g_nfsq[i * Bdim + row];
        s_nf = fmaxf(sqrtf(s), 1e-8f);
    }
    __syncthreads();

    float logit = -CUDART_INF_F;
    if (t < Cdim) {
        float g = 0.f;
        for (int s = 0; s < SPLITS; s++)
            g += g_part[((size_t)s * Bdim + row) * CPAD + t];
        logit = 10.0f * g / (s_nf * g_wn[t]);
    }
    slog[t] = logit;
    sv[t]   = logit;
    si[t]   = t;
    __syncthreads();

    for (int off = 64; off > 0; off >>= 1) {
        if (t < off) {
            float v2 = sv[t + off]; int i2 = si[t + off];
            if (v2 > sv[t] || (v2 == sv[t] && i2 < si[t])) { sv[t] = v2; si[t] = i2; }
        }
        __syncthreads();
    }
    const float mx   = sv[0];
    const int   amax = si[0];
    __syncthreads();

    sv[t] = (t < Cdim) ? expf(logit - mx) : 0.f;
    __syncthreads();
    for (int off = 64; off > 0; off >>= 1) {
        if (t < off) sv[t] += sv[t + off];
        __syncthreads();
    }

    if (t == 0) {
        const float lse = logf(sv[0]) + mx;
        long long lab;
        if (g_is64) lab = ((const long long*)labels)[row];
        else        lab = (long long)((const int*)labels)[row];
        const bool valid = (lab >= 0);
        float nll = 0.f, corr = 0.f;
        if (valid) {
            nll  = lse - slog[(int)lab];
            corr = (amax == (int)lab) ? 1.f : 0.f;
        }
        g_nll[row]  = nll;
        g_corr[row] = corr;
        g_vld[row]  = valid ? 1.f : 0.f;
    }
}

// ======================= finalize =======================
__global__ __launch_bounds__(256) void finalize_kernel(float* __restrict__ out,
                                                       int out_size) {
    __shared__ float sn[256], sc[256], sd[256];
    const int t = threadIdx.x;
    float a = 0.f, b = 0.f, c = 0.f;
    for (int i = t; i < Bdim; i += 256) {
        a += g_nll[i]; b += g_corr[i]; c += g_vld[i];
    }
    sn[t] = a; sc[t] = b; sd[t] = c;
    __syncthreads();
    for (int off = 128; off > 0; off >>= 1) {
        if (t < off) { sn[t] += sn[t + off]; sc[t] += sc[t + off]; sd[t] += sd[t + off]; }
        __syncthreads();
    }
    if (t == 0) {
        const float nv = sd[0];
        out[0] = sn[0] / fmaxf(nv, 1.0f);
        if (out_size > 1) out[1] = sc[0] / (nv + 1e-10f);
    }
}

// ======================= launch =======================
extern "C" void kernel_launch(void* const* d_in, const int* in_sizes, int n_in,
                              void* d_out, int out_size) {
    int fi = 0, li = 0;
    for (int i = 1; i < n_in; i++) {
        if (in_sizes[i] > in_sizes[fi]) fi = i;
        if (in_sizes[i] < in_sizes[li]) li = i;
    }
    int wi = 0;
    for (int i = 0; i < n_in; i++) if (i != fi && i != li) wi = i;

    const float* F = (const float*)d_in[fi];
    const float* W = (const float*)d_in[wi];
    const void*  L = d_in[li];
    const int nlab = in_sizes[li];

    cudaFuncSetAttribute(gemm_mma_kernel,
                         cudaFuncAttributeMaxDynamicSharedMemorySize, SMEM_TOTAL);

    detect_label_kernel<<<1, 32>>>((const int*)L, nlab);
    wnorm_kernel<<<CPAD, 256>>>(W);
    gemm_mma_kernel<<<dim3(Bdim / BM, SPLITS), 512, SMEM_TOTAL>>>(F, W);
    epilogue_kernel<<<Bdim, 128>>>(L);
    finalize_kernel<<<1, 256>>>((float*)d_out, out_size);
}